// round 4
// baseline (speedup 1.0000x reference)
#include <cuda_runtime.h>

#define SEQ 2048
#define BB  64
#define IND 512
#define HH  512
#define H3  1536
#define NCTA 128
#define NTHR 256

typedef unsigned long long ull;

// ---------------- global scratch (static device memory: allowed) ----------------
__device__ float g_gx[(size_t)SEQ * BB * H3];   // precomputed input projections (+bias)
__device__ float g_h[BB * HH];                  // current hidden state
__device__ float g_z[BB * HH];                  // z gate values
__device__ float g_rh[BB * HH];                 // r * h_prev
__device__ unsigned g_bar;                      // grid barrier counter

// ---------------- helpers ----------------
__device__ __forceinline__ ull ffma2(ull a, ull b, ull c) {
    ull d;
    asm("fma.rn.f32x2 %0, %1, %2, %3;" : "=l"(d) : "l"(a), "l"(b), "l"(c));
    return d;
}
__device__ __forceinline__ float2 u2f2(ull v) {
    float2 r;
    r.x = __uint_as_float((unsigned)(v & 0xffffffffULL));
    r.y = __uint_as_float((unsigned)(v >> 32));
    return r;
}
__device__ __forceinline__ float sigmoidf_(float x) {
    return 1.0f / (1.0f + __expf(-x));
}
__device__ __forceinline__ float tanhf_(float x) {
    return 1.0f - 2.0f / (__expf(2.0f * x) + 1.0f);
}

__device__ __forceinline__ void grid_bar(unsigned goal) {
    __syncthreads();
    if (threadIdx.x == 0) {
        __threadfence();
        atomicAdd(&g_bar, 1u);
        unsigned v;
        do {
            asm volatile("ld.acquire.gpu.u32 %0, [%1];" : "=r"(v) : "l"(&g_bar) : "memory");
        } while (v < goal);
    }
    __syncthreads();
}

// ---------------- init: reset barrier, load h0 ----------------
__global__ void init_kernel(const float* __restrict__ h0) {
    int i = blockIdx.x * blockDim.x + threadIdx.x;
    if (i == 0) g_bar = 0u;
    if (i < BB * HH) g_h[i] = h0[i];
}

// ---------------- precompute: gx = x @ [Wg_x | Wc_x] + [bg | bc] ----------------
// M = SEQ*BB = 131072, K = 512, N = 1536. 128x128 tile, BK=8, 256 threads,
// 8x8 micro-tile computed as 8x(4 col-pairs) with fma.rn.f32x2.
__global__ void __launch_bounds__(NTHR) precompute_kernel(
    const float* __restrict__ x, const float* __restrict__ Wg,
    const float* __restrict__ bg, const float* __restrict__ Wc,
    const float* __restrict__ bc)
{
    __shared__ float2 as2[8 * 128];  // A values duplicated: (a,a), indexed [k][row]
    __shared__ float2 bs2[8 * 64];   // B col-pairs: (b[2c],b[2c+1]), indexed [k][cpair]

    const int bx = blockIdx.x;          // 0..11 N-tiles (8 for Wg, 4 for Wc)
    const int m0 = blockIdx.y * 128;    // 0..1023 M-tiles

    const float* Wp; const float* bias; int ldw, n0;
    if (bx < 8) { Wp = Wg; bias = bg; ldw = 1024; n0 = bx * 128; }
    else        { Wp = Wc; bias = bc; ldw = 512;  n0 = (bx - 8) * 128; }

    const int tid = threadIdx.x;
    const int tx = tid & 15, ty = tid >> 4;

    const int arow = tid >> 1, acol = (tid & 1) * 4;
    const int bkrow = tid >> 5, bcol2 = (tid & 31) * 2;   // float2 col index

    const float* aptr = x + (size_t)(m0 + arow) * IND + acol;
    const float* bptr = Wp + (size_t)bkrow * ldw + n0 + bcol2 * 2;

    float4 areg = *(const float4*)aptr;
    float4 breg = *(const float4*)bptr;

    ull acc[8][4];
#pragma unroll
    for (int i = 0; i < 8; ++i)
#pragma unroll
        for (int j = 0; j < 4; ++j) acc[i][j] = 0ULL;

    for (int kt = 0; kt < IND / 8; ++kt) {
        as2[(acol + 0) * 128 + arow] = make_float2(areg.x, areg.x);
        as2[(acol + 1) * 128 + arow] = make_float2(areg.y, areg.y);
        as2[(acol + 2) * 128 + arow] = make_float2(areg.z, areg.z);
        as2[(acol + 3) * 128 + arow] = make_float2(areg.w, areg.w);
        *(float4*)&bs2[bkrow * 64 + bcol2] = breg;  // (x,y),(z,w) = 2 col-pairs
        __syncthreads();
        if (kt + 1 < IND / 8) {
            areg = *(const float4*)(aptr + (kt + 1) * 8);
            breg = *(const float4*)(bptr + (size_t)(kt + 1) * 8 * ldw);
        }
#pragma unroll
        for (int k = 0; k < 8; ++k) {
            ulonglong2 a01 = *(const ulonglong2*)&as2[k * 128 + ty * 8];
            ulonglong2 a23 = *(const ulonglong2*)&as2[k * 128 + ty * 8 + 2];
            ulonglong2 a45 = *(const ulonglong2*)&as2[k * 128 + ty * 8 + 4];
            ulonglong2 a67 = *(const ulonglong2*)&as2[k * 128 + ty * 8 + 6];
            ulonglong2 b01 = *(const ulonglong2*)&bs2[k * 64 + tx * 4];
            ulonglong2 b23 = *(const ulonglong2*)&bs2[k * 64 + tx * 4 + 2];
            ull av[8] = {a01.x, a01.y, a23.x, a23.y, a45.x, a45.y, a67.x, a67.y};
            ull bv[4] = {b01.x, b01.y, b23.x, b23.y};
#pragma unroll
            for (int i = 0; i < 8; ++i)
#pragma unroll
                for (int j = 0; j < 4; ++j)
                    acc[i][j] = ffma2(av[i], bv[j], acc[i][j]);
        }
        __syncthreads();
    }

    float bvl[8];
#pragma unroll
    for (int j = 0; j < 8; ++j) bvl[j] = bias[n0 + tx * 8 + j];

#pragma unroll
    for (int i = 0; i < 8; ++i) {
        size_t row = (size_t)m0 + ty * 8 + i;
        float* op = g_gx + row * H3 + bx * 128 + tx * 8;  // bx*128 maps both regions
        float2 c0 = u2f2(acc[i][0]);
        float2 c1 = u2f2(acc[i][1]);
        float2 c2 = u2f2(acc[i][2]);
        float2 c3 = u2f2(acc[i][3]);
        *(float4*)(op)     = make_float4(c0.x + bvl[0], c0.y + bvl[1],
                                         c1.x + bvl[2], c1.y + bvl[3]);
        *(float4*)(op + 4) = make_float4(c2.x + bvl[4], c2.y + bvl[5],
                                         c3.x + bvl[6], c3.y + bvl[7]);
    }
}

// ---------------- persistent scan kernel ----------------
// 128 CTAs x 256 threads, all co-resident. CTA c: rows [ (c>>5)*16, +16 ),
// phase1 gate cols [ (c&31)*32, +32 ) of 1024, phase2 h cols [ (c&31)*16, +16 ).
// Recurrent weight slabs live in smem for the whole scan.
// smem float layout:
//   wp1   : 16 col-pairs x 514 float2 (Wg_h pairs, padded)   = 16448 floats
//   wcs   : 16 cols      x 516 float  (Wc_h, padded)         =  8256 floats
//   stage : 16 rows x 514 float2 (h duplicated, phase1)
//           reused as 16 rows x 516 float (rh plain, phase2) = 16448 floats
#define SMEM_FLOATS (16448 + 8256 + 16448)
#define SMEM_BYTES  (SMEM_FLOATS * 4)

__global__ void __launch_bounds__(NTHR, 1) scan_kernel(
    const float* __restrict__ Wg, const float* __restrict__ Wc,
    float* __restrict__ out, int write_outputs, int write_hlast)
{
    extern __shared__ float smem[];
    float2* wp1    = (float2*)smem;
    float*  wcs    = smem + 16448;
    float2* stage2 = (float2*)(smem + 16448 + 8256);
    float*  stageF = smem + 16448 + 8256;

    const int tid = threadIdx.x;
    const int cta = blockIdx.x;
    const int rg  = cta >> 5;
    const int cg  = cta & 31;
    const int r0  = rg * 16;
    const int gc0 = cg * 32;   // gate col base (of 1024)
    const int hc0 = cg * 16;   // hidden col base (of 512)

    // --- load recurrent weight slabs once ---
    for (int idx = tid; idx < 16 * 512; idx += NTHR) {
        int cp = idx & 15, k = idx >> 4;
        const float* ws = Wg + (size_t)(512 + k) * 1024 + gc0 + 2 * cp;
        wp1[cp * 514 + k] = make_float2(ws[0], ws[1]);
    }
    for (int idx = tid; idx < 16 * 512; idx += NTHR) {
        int lc = idx & 15, k = idx >> 4;
        wcs[lc * 516 + k] = Wc[(size_t)(512 + k) * 512 + hc0 + lc];
    }
    __syncthreads();

    const int lrow = tid >> 4;   // 0..15
    const int lcp  = tid & 15;   // phase1 col-pair / phase2 col
    unsigned barcnt = 0;

    for (int t = 0; t < SEQ; ++t) {
        // ---- stage h (duplicated pairs) ----
#pragma unroll
        for (int i = 0; i < 8; ++i) {
            int idx4 = tid + i * NTHR;          // 2048 float4s = 16 rows x 512
            int lr = idx4 >> 7, k4 = idx4 & 127;
            float4 v = __ldcg((const float4*)(g_h + (size_t)(r0 + lr) * HH + k4 * 4));
            float2* dst = stage2 + lr * 514 + k4 * 4;
            *(float4*)(dst)     = make_float4(v.x, v.x, v.y, v.y);
            *(float4*)(dst + 2) = make_float4(v.z, v.z, v.w, v.w);
        }
        __syncthreads();

        // ---- phase1: gates GEMM (2 packed cols per thread, full k) ----
        {
            const ulonglong2* hp = (const ulonglong2*)(stage2 + lrow * 514);
            const ulonglong2* wp = (const ulonglong2*)(wp1 + lcp * 514);
            ull acc0 = 0ULL, acc1 = 0ULL;
#pragma unroll 8
            for (int i = 0; i < 256; ++i) {
                ulonglong2 hv = hp[i];
                ulonglong2 wv = wp[i];
                acc0 = ffma2(hv.x, wv.x, acc0);
                acc1 = ffma2(hv.y, wv.y, acc1);
            }
            float2 s0 = u2f2(acc0), s1 = u2f2(acc1);
            int grow = r0 + lrow;
            int col0 = gc0 + 2 * lcp;
            const float* gxp = g_gx + ((size_t)t * BB + grow) * H3 + col0;
            float p0 = s0.x + s1.x + gxp[0];
            float p1 = s0.y + s1.y + gxp[1];
            if (gc0 < 512) {
                __stcg(g_z + grow * HH + col0,     sigmoidf_(p0));
                __stcg(g_z + grow * HH + col0 + 1, sigmoidf_(p1));
            } else {
                int hk = col0 - 512;
                float hp0 = stage2[lrow * 514 + hk].x;
                float hp1 = stage2[lrow * 514 + hk + 1].x;
                __stcg(g_rh + grow * HH + hk,     sigmoidf_(p0) * hp0);
                __stcg(g_rh + grow * HH + hk + 1, sigmoidf_(p1) * hp1);
            }
        }

        barcnt += NCTA;
        grid_bar(barcnt);

        // ---- stage rh (plain) ----
#pragma unroll
        for (int i = 0; i < 8; ++i) {
            int idx4 = tid + i * NTHR;
            int lr = idx4 >> 7, k4 = idx4 & 127;
            float4 v = __ldcg((const float4*)(g_rh + (size_t)(r0 + lr) * HH + k4 * 4));
            *(float4*)(stageF + lr * 516 + k4 * 4) = v;
        }
        __syncthreads();

        // ---- phase2: candidate GEMM (k-pair packed) + h update ----
        {
            const ulonglong2* hp = (const ulonglong2*)(stageF + lrow * 516);
            const ulonglong2* wp = (const ulonglong2*)(wcs + lcp * 516);
            ull acc0 = 0ULL, acc1 = 0ULL;
#pragma unroll 8
            for (int i = 0; i < 128; ++i) {
                ulonglong2 hv = hp[i];
                ulonglong2 wv = wp[i];
                acc0 = ffma2(hv.x, wv.x, acc0);
                acc1 = ffma2(hv.y, wv.y, acc1);
            }
            float2 s0 = u2f2(acc0), s1 = u2f2(acc1);
            float dot = (s0.x + s0.y) + (s1.x + s1.y);
            int grow = r0 + lrow;
            int col  = hc0 + lcp;
            float cx = g_gx[((size_t)t * BB + grow) * H3 + 1024 + col];
            float cand = tanhf_(cx + dot);
            float z   = __ldcg(g_z + grow * HH + col);
            float hpv = __ldcg(g_h + grow * HH + col);
            float hn  = fmaf(z, cand - hpv, hpv);   // (1-z)*h + z*cand
            if (write_outputs)
                out[((size_t)t * BB + grow) * HH + col] = hn;
            __stcg(g_h + grow * HH + col, hn);
            if (write_hlast && t == SEQ - 1) {
                size_t off = write_outputs ? (size_t)SEQ * BB * HH : 0;
                out[off + grow * HH + col] = hn;
            }
        }

        barcnt += NCTA;
        grid_bar(barcnt);
    }
}

// ---------------- launch ----------------
extern "C" void kernel_launch(void* const* d_in, const int* in_sizes, int n_in,
                              void* d_out, int out_size) {
    const float* x  = (const float*)d_in[0];
    const float* h0 = (const float*)d_in[1];
    const float* Wg = (const float*)d_in[2];
    const float* bg = (const float*)d_in[3];
    const float* Wc = (const float*)d_in[4];
    const float* bc = (const float*)d_in[5];
    float* out = (float*)d_out;

    cudaFuncSetAttribute(scan_kernel, cudaFuncAttributeMaxDynamicSharedMemorySize,
                         SMEM_BYTES);

    long long full = (long long)SEQ * BB * HH;
    int write_outputs = (out_size >= full) ? 1 : 0;
    long long hlast_off = write_outputs ? full : 0;
    int write_hlast = (out_size >= hlast_off + BB * HH) ? 1 : 0;

    init_kernel<<<128, 256>>>(h0);
    dim3 pgrid(12, 1024);
    precompute_kernel<<<pgrid, NTHR>>>(x, Wg, bg, Wc, bc);
    scan_kernel<<<NCTA, NTHR, SMEM_BYTES>>>(Wg, Wc, out, write_outputs, write_hlast);
}

// round 6
// speedup vs baseline: 1.4663x; 1.4663x over previous
#include <cuda_runtime.h>

#define SEQ 2048
#define BB  64
#define IND 512
#define HH  512
#define H3  1536
#define NCTA 128
#define NTHR 256

typedef unsigned long long ull;

// ---------------- global scratch (static device memory: allowed) ----------------
// gx layout: [t][group(2)][cta(64)] blocks of 32 rows x 24 cols (16 gate + 8 cand),
// biases folded in. Block = 768 floats, contiguous.
__device__ float g_gx[(size_t)SEQ * 2 * 64 * 768];
__device__ float g_h[BB * HH];      // current hidden state
__device__ float g_rh[BB * HH];     // r * h_prev
__device__ unsigned g_ctr[4];       // barriers: [A_g0, A_g1, B_g0, B_g1]

// ---------------- helpers ----------------
__device__ __forceinline__ ull ffma2(ull a, ull b, ull c) {
    ull d;
    asm("fma.rn.f32x2 %0, %1, %2, %3;" : "=l"(d) : "l"(a), "l"(b), "l"(c));
    return d;
}
__device__ __forceinline__ float ull_sum(ull v) {
    return __uint_as_float((unsigned)(v & 0xffffffffULL)) +
           __uint_as_float((unsigned)(v >> 32));
}
__device__ __forceinline__ float sigmoidf_(float x) {
    return 1.0f / (1.0f + __expf(-x));
}
__device__ __forceinline__ float tanhf_(float x) {
    return 1.0f - 2.0f / (__expf(2.0f * x) + 1.0f);
}
__device__ __forceinline__ void bar_arrive(unsigned* ctr) {
    __syncthreads();
    if (threadIdx.x == 0)
        asm volatile("red.release.gpu.global.add.u32 [%0], %1;"
                     :: "l"(ctr), "r"(1u) : "memory");
}
__device__ __forceinline__ void bar_wait(unsigned* ctr, unsigned goal) {
    if (threadIdx.x == 0) {
        unsigned v;
        asm volatile("ld.acquire.gpu.u32 %0, [%1];" : "=r"(v) : "l"(ctr) : "memory");
        while (v < goal) {
            __nanosleep(32);
            asm volatile("ld.acquire.gpu.u32 %0, [%1];" : "=r"(v) : "l"(ctr) : "memory");
        }
    }
    __syncthreads();
}

// ---------------- precompute: gx = x @ [Wg_x | Wc_x] + [bg | bc], remapped ----
// M = SEQ*BB = 131072, K = 512, N = 1536. 128x128 tile, BK=8, fma.rn.f32x2.
// Block (0,0) additionally copies h0 -> g_h and resets barrier counters.
__global__ void __launch_bounds__(NTHR) precompute_kernel(
    const float* __restrict__ x, const float* __restrict__ Wg,
    const float* __restrict__ bg, const float* __restrict__ Wc,
    const float* __restrict__ bc, const float* __restrict__ h0)
{
    __shared__ float2 as2[8 * 128];  // A duplicated (a,a), [k][row]
    __shared__ float2 bs2[8 * 64];   // B col-pairs, [k][cpair]

    const int tid = threadIdx.x;

    if (blockIdx.x == 0 && blockIdx.y == 0) {
        for (int i = tid; i < BB * HH; i += NTHR) g_h[i] = h0[i];
        if (tid < 4) g_ctr[tid] = 0u;
    }

    const int bx = blockIdx.x;          // 0..11 (8 Wg tiles, 4 Wc tiles)
    const int m0 = blockIdx.y * 128;

    const float* Wp; const float* bias; int ldw, n0;
    if (bx < 8) { Wp = Wg; bias = bg; ldw = 1024; n0 = bx * 128; }
    else        { Wp = Wc; bias = bc; ldw = 512;  n0 = (bx - 8) * 128; }

    const int tx = tid & 15, ty = tid >> 4;
    const int arow = tid >> 1, acol = (tid & 1) * 4;
    const int bkrow = tid >> 5, bcol2 = (tid & 31) * 2;

    const float* aptr = x + (size_t)(m0 + arow) * IND + acol;
    const float* bptr = Wp + (size_t)bkrow * ldw + n0 + bcol2 * 2;

    float4 areg = *(const float4*)aptr;
    float4 breg = *(const float4*)bptr;

    ull acc[8][4];
#pragma unroll
    for (int i = 0; i < 8; ++i)
#pragma unroll
        for (int j = 0; j < 4; ++j) acc[i][j] = 0ULL;

    for (int kt = 0; kt < IND / 8; ++kt) {
        as2[(acol + 0) * 128 + arow] = make_float2(areg.x, areg.x);
        as2[(acol + 1) * 128 + arow] = make_float2(areg.y, areg.y);
        as2[(acol + 2) * 128 + arow] = make_float2(areg.z, areg.z);
        as2[(acol + 3) * 128 + arow] = make_float2(areg.w, areg.w);
        *(float4*)&bs2[bkrow * 64 + bcol2] = breg;
        __syncthreads();
        if (kt + 1 < IND / 8) {
            areg = *(const float4*)(aptr + (kt + 1) * 8);
            breg = *(const float4*)(bptr + (size_t)(kt + 1) * 8 * ldw);
        }
#pragma unroll
        for (int k = 0; k < 8; ++k) {
            ulonglong2 a01 = *(const ulonglong2*)&as2[k * 128 + ty * 8];
            ulonglong2 a23 = *(const ulonglong2*)&as2[k * 128 + ty * 8 + 2];
            ulonglong2 a45 = *(const ulonglong2*)&as2[k * 128 + ty * 8 + 4];
            ulonglong2 a67 = *(const ulonglong2*)&as2[k * 128 + ty * 8 + 6];
            ulonglong2 b01 = *(const ulonglong2*)&bs2[k * 64 + tx * 4];
            ulonglong2 b23 = *(const ulonglong2*)&bs2[k * 64 + tx * 4 + 2];
            ull av[8] = {a01.x, a01.y, a23.x, a23.y, a45.x, a45.y, a67.x, a67.y};
            ull bv[4] = {b01.x, b01.y, b23.x, b23.y};
#pragma unroll
            for (int i = 0; i < 8; ++i)
#pragma unroll
                for (int j = 0; j < 4; ++j)
                    acc[i][j] = ffma2(av[i], bv[j], acc[i][j]);
        }
        __syncthreads();
    }

    float bvl[8];
#pragma unroll
    for (int j = 0; j < 8; ++j) bvl[j] = bias[n0 + tx * 8 + j];

    // Destination remap: (bx, tx) -> (cta, slot); depends only on column chunk.
    int cta, slot;
    if (bx < 8) {
        int gcol = bx * 128 + tx * 8;
        if (gcol < 512) { cta = gcol >> 3;          slot = 0; }
        else            { cta = (gcol - 512) >> 3;  slot = 8; }
    } else {
        int ccol = (bx - 8) * 128 + tx * 8;
        cta = ccol >> 3; slot = 16;
    }

#pragma unroll
    for (int i = 0; i < 8; ++i) {
        int m = m0 + ty * 8 + i;
        int t = m >> 6, b = m & 63, g = b >> 5, r = b & 31;
        float* op = g_gx + (((size_t)t * 2 + g) * 64 + cta) * 768 + r * 24 + slot;
        float2 c0, c1, c2, c3;
        c0.x = __uint_as_float((unsigned)acc[i][0]); c0.y = __uint_as_float((unsigned)(acc[i][0] >> 32));
        c1.x = __uint_as_float((unsigned)acc[i][1]); c1.y = __uint_as_float((unsigned)(acc[i][1] >> 32));
        c2.x = __uint_as_float((unsigned)acc[i][2]); c2.y = __uint_as_float((unsigned)(acc[i][2] >> 32));
        c3.x = __uint_as_float((unsigned)acc[i][3]); c3.y = __uint_as_float((unsigned)(acc[i][3] >> 32));
        *(float4*)(op)     = make_float4(c0.x + bvl[0], c0.y + bvl[1],
                                         c1.x + bvl[2], c1.y + bvl[3]);
        *(float4*)(op + 4) = make_float4(c2.x + bvl[4], c2.y + bvl[5],
                                         c3.x + bvl[6], c3.y + bvl[7]);
    }
}

// ---------------- persistent scan kernel ----------------
// 128 CTAs x 256 thr, 1/SM. group g = bid>>6 owns rows [g*32, g*32+32).
// cid = bid&63: phase1 gate cols z:[cid*8,+8) r:[512+cid*8,+8); phase2 cand cols [cid*8,+8).
// smem (floats):
//   hstage  32x512 (XOR-swizzled by (row>>2)&7 on float4 chunks)  16384
//   rhstage 32x512 (swizzled by (row>>1)&7)                       16384
//   wg1     16 cols x 512 (swizzled by col>>2)                     8192
//   wc1      8 cols x 512 (swizzled by col>>2)                     4096
//   P       partials [kslice][v][lane]                             4096
//   gxbuf   768, zbuf 256
#define SM_H   0
#define SM_RH  16384
#define SM_WG  32768
#define SM_WC  40960
#define SM_P   45056
#define SM_GX  49152
#define SM_Z   49920
#define SMEM_FLOATS 50176
#define SMEM_BYTES (SMEM_FLOATS * 4)

__global__ void __launch_bounds__(NTHR, 1) scan_kernel(
    const float* __restrict__ Wg, const float* __restrict__ Wc,
    float* __restrict__ out, int write_outputs, int write_hlast)
{
    extern __shared__ float sm[];
    float* hst  = sm + SM_H;
    float* rhst = sm + SM_RH;
    float* wg1  = sm + SM_WG;
    float* wc1  = sm + SM_WC;
    float* P    = sm + SM_P;
    float* gxb  = sm + SM_GX;
    float* zb   = sm + SM_Z;

    const int tid = threadIdx.x;
    const int g   = blockIdx.x >> 6;
    const int cid = blockIdx.x & 63;
    const int r0  = g * 32;
    const int c8  = cid * 8;

    // ---- load recurrent weight slabs once (swizzled) ----
    for (int idx = tid; idx < 16 * 512; idx += NTHR) {
        int c = idx >> 9, k = idx & 511;
        int gc = (c < 8) ? (c8 + c) : (512 + c8 + (c - 8));
        float v = Wg[(size_t)(512 + k) * 1024 + gc];
        int kc = k >> 2, s = (c >> 2) & 7;
        wg1[c * 512 + ((kc ^ s) << 2) + (k & 3)] = v;
    }
    for (int idx = tid; idx < 8 * 512; idx += NTHR) {
        int c = idx >> 9, k = idx & 511;
        float v = Wc[(size_t)(512 + k) * 512 + c8 + c];
        int kc = k >> 2, s = (c >> 2) & 7;
        wc1[c * 512 + ((kc ^ s) << 2) + (k & 3)] = v;
    }
    __syncthreads();

    // phase1 thread mapping
    const int ks  = tid >> 5;
    const int ln  = tid & 31;
    const int cg  = ln & 3;        // col group (4 cols each)
    const int rg  = ln >> 2;       // row group (4 rows each), 0..7
    // phase1 reducer mapping
    const int rrg = ln & 7, rcg = ln >> 3;      // (rg, cg) for reduce
    const int rlane1 = rcg + 4 * rrg;
    // phase2 thread mapping
    const int cg2 = ln & 1;
    const int rg2 = ln >> 1;       // 0..15
    // phase2 reducer mapping
    const int rrg2 = ln & 15, rcg2 = ln >> 4;
    const int rlane2 = rcg2 + 2 * rrg2;

    unsigned* ctrA = &g_ctr[g];
    unsigned* ctrB = &g_ctr[2 + g];

    for (int t = 0; t < SEQ; ++t) {
        // ---- stage gx block (3 KB) + h (64 KB) ----
        if (tid < 192) {
            const float4* src = (const float4*)(g_gx + (((size_t)t * 2 + g) * 64 + cid) * 768);
            *(float4*)&gxb[tid * 4] = __ldcg(src + tid);
        }
#pragma unroll 4
        for (int it = 0; it < 16; ++it) {
            int id = tid + it * NTHR;
            int lr = id >> 7, kc = id & 127;
            float4 v = __ldcg((const float4*)(g_h + (size_t)(r0 + lr) * HH + kc * 4));
            *(float4*)&hst[lr * 512 + ((kc ^ ((lr >> 2) & 7)) << 2)] = v;
        }
        __syncthreads();

        // ---- phase1: gates GEMM, thread = 4 rows x 4 cols x 64 k ----
        {
            ull acc[4][4];
#pragma unroll
            for (int i = 0; i < 4; ++i)
#pragma unroll
                for (int j = 0; j < 4; ++j) acc[i][j] = 0ULL;

            const int kc0 = ks * 16;
#pragma unroll 4
            for (int tt = 0; tt < 16; ++tt) {
                int kc = kc0 + tt;
                ulonglong2 hv[4], wv[4];
#pragma unroll
                for (int i = 0; i < 4; ++i)
                    hv[i] = *(const ulonglong2*)&hst[(rg * 4 + i) * 512 + ((kc ^ rg) << 2)];
#pragma unroll
                for (int j = 0; j < 4; ++j)
                    wv[j] = *(const ulonglong2*)&wg1[(cg * 4 + j) * 512 + ((kc ^ cg) << 2)];
#pragma unroll
                for (int i = 0; i < 4; ++i)
#pragma unroll
                    for (int j = 0; j < 4; ++j) {
                        acc[i][j] = ffma2(hv[i].x, wv[j].x, acc[i][j]);
                        acc[i][j] = ffma2(hv[i].y, wv[j].y, acc[i][j]);
                    }
            }
#pragma unroll
            for (int i = 0; i < 4; ++i)
#pragma unroll
                for (int j = 0; j < 4; ++j)
                    P[(ks * 16 + i * 4 + j) * 32 + ln] = ull_sum(acc[i][j]);
        }
        __syncthreads();

        // ---- phase1 reduce + epilogue (z local, rh -> global) ----
#pragma unroll
        for (int vv = 0; vv < 2; ++vv) {
            int v = ks + vv * 8;           // 0..15
            int i = v >> 2, j = v & 3;
            int row = rrg * 4 + i, col = rcg * 4 + j;
            float s = 0.f;
#pragma unroll
            for (int q = 0; q < 8; ++q) s += P[(q * 16 + v) * 32 + rlane1];
            float tot = s + gxb[row * 24 + col];
            float sg = sigmoidf_(tot);
            if (col < 8) {
                zb[row * 8 + col] = sg;
            } else {
                int jj = c8 + (col - 8);
                float hv = hst[row * 512 + (((jj >> 2) ^ ((row >> 2) & 7)) << 2) + (jj & 3)];
                __stcg(g_rh + (size_t)(r0 + row) * HH + jj, sg * hv);
            }
        }

        bar_arrive(ctrA);
        bar_wait(ctrA, (unsigned)(t + 1) * 64u);

        // ---- stage rh ----
#pragma unroll 4
        for (int it = 0; it < 16; ++it) {
            int id = tid + it * NTHR;
            int lr = id >> 7, kc = id & 127;
            float4 v = __ldcg((const float4*)(g_rh + (size_t)(r0 + lr) * HH + kc * 4));
            *(float4*)&rhst[lr * 512 + ((kc ^ ((lr >> 1) & 7)) << 2)] = v;
        }
        __syncthreads();

        // ---- phase2: candidate GEMM, thread = 2 rows x 4 cols x 64 k ----
        {
            ull acc[2][4];
#pragma unroll
            for (int i = 0; i < 2; ++i)
#pragma unroll
                for (int j = 0; j < 4; ++j) acc[i][j] = 0ULL;

            const int kc0 = ks * 16;
#pragma unroll 4
            for (int tt = 0; tt < 16; ++tt) {
                int kc = kc0 + tt;
                ulonglong2 hv[2], wv[4];
#pragma unroll
                for (int i = 0; i < 2; ++i)
                    hv[i] = *(const ulonglong2*)&rhst[(rg2 * 2 + i) * 512 + ((kc ^ (rg2 & 7)) << 2)];
#pragma unroll
                for (int j = 0; j < 4; ++j)
                    wv[j] = *(const ulonglong2*)&wc1[(cg2 * 4 + j) * 512 + ((kc ^ cg2) << 2)];
#pragma unroll
                for (int i = 0; i < 2; ++i)
#pragma unroll
                    for (int j = 0; j < 4; ++j) {
                        acc[i][j] = ffma2(hv[i].x, wv[j].x, acc[i][j]);
                        acc[i][j] = ffma2(hv[i].y, wv[j].y, acc[i][j]);
                    }
            }
#pragma unroll
            for (int i = 0; i < 2; ++i)
#pragma unroll
                for (int j = 0; j < 4; ++j)
                    P[(ks * 8 + i * 4 + j) * 32 + ln] = ull_sum(acc[i][j]);
        }
        __syncthreads();

        // ---- phase2 reduce + h update ----
        {
            int v = ks;                    // 0..7
            int i = v >> 2, j = v & 3;
            int row = rrg2 * 2 + i, col = rcg2 * 4 + j;
            float s = 0.f;
#pragma unroll
            for (int q = 0; q < 8; ++q) s += P[(q * 8 + v) * 32 + rlane2];
            float cand = tanhf_(s + gxb[row * 24 + 16 + col]);
            float z = zb[row * 8 + col];
            int jj = c8 + col;
            float hprev = hst[row * 512 + (((jj >> 2) ^ ((row >> 2) & 7)) << 2) + (jj & 3)];
            float hn = fmaf(z, cand - hprev, hprev);
            int b = r0 + row;
            __stcg(g_h + (size_t)b * HH + jj, hn);
            if (write_outputs)
                out[((size_t)t * BB + b) * HH + jj] = hn;
            if (write_hlast && t == SEQ - 1) {
                size_t off = write_outputs ? (size_t)SEQ * BB * HH : 0;
                out[off + (size_t)b * HH + jj] = hn;
            }
        }

        bar_arrive(ctrB);
        bar_wait(ctrB, (unsigned)(t + 1) * 64u);
    }
}

// ---------------- launch ----------------
extern "C" void kernel_launch(void* const* d_in, const int* in_sizes, int n_in,
                              void* d_out, int out_size) {
    const float* x  = (const float*)d_in[0];
    const float* h0 = (const float*)d_in[1];
    const float* Wg = (const float*)d_in[2];
    const float* bg = (const float*)d_in[3];
    const float* Wc = (const float*)d_in[4];
    const float* bc = (const float*)d_in[5];
    float* out = (float*)d_out;

    cudaFuncSetAttribute(scan_kernel, cudaFuncAttributeMaxDynamicSharedMemorySize,
                         SMEM_BYTES);

    long long full = (long long)SEQ * BB * HH;
    int write_outputs = (out_size >= full) ? 1 : 0;
    long long hlast_off = write_outputs ? full : 0;
    int write_hlast = (out_size >= hlast_off + BB * HH) ? 1 : 0;

    dim3 pgrid(12, 1024);
    precompute_kernel<<<pgrid, NTHR>>>(x, Wg, bg, Wc, bc, h0);
    scan_kernel<<<NCTA, NTHR, SMEM_BYTES>>>(Wg, Wc, out, write_outputs, write_hlast);
}

// round 7
// speedup vs baseline: 1.7502x; 1.1935x over previous
#include <cuda_runtime.h>

#define SEQ 2048
#define BB  64
#define IND 512
#define HH  512
#define NCTA 128
#define NTHR 256

typedef unsigned long long ull;

// ---------------- global scratch (static device memory: allowed) ----------------
// gx layout: [t][group(8)][cta(16)] blocks of 8 rows x 96 cols
// (cols 0-31 z-pre, 32-63 r-pre, 64-95 cand-pre), biases folded. Block = 768 floats.
__device__ float g_gx[(size_t)SEQ * 8 * 16 * 768];
__device__ float g_h[BB * HH];        // current hidden state
__device__ float g_rh[BB * HH];       // r * h_prev
__device__ unsigned g_ctr[16 * 32];   // 16 barrier counters, padded to 128B lines

// ---------------- helpers ----------------
__device__ __forceinline__ ull ffma2(ull a, ull b, ull c) {
    ull d;
    asm("fma.rn.f32x2 %0, %1, %2, %3;" : "=l"(d) : "l"(a), "l"(b), "l"(c));
    return d;
}
__device__ __forceinline__ float ull_sum(ull v) {
    return __uint_as_float((unsigned)(v & 0xffffffffULL)) +
           __uint_as_float((unsigned)(v >> 32));
}
__device__ __forceinline__ float sigmoidf_(float x) {
    return 1.0f / (1.0f + __expf(-x));
}
__device__ __forceinline__ float tanhf_(float x) {
    return 1.0f - 2.0f / (__expf(2.0f * x) + 1.0f);
}
__device__ __forceinline__ void bar_arrive(unsigned* ctr) {
    __syncthreads();
    if (threadIdx.x == 0)
        asm volatile("red.release.gpu.global.add.u32 [%0], %1;"
                     :: "l"(ctr), "r"(1u) : "memory");
}
__device__ __forceinline__ void bar_wait(unsigned* ctr, unsigned goal) {
    if (threadIdx.x == 0) {
        unsigned v;
        asm volatile("ld.acquire.gpu.u32 %0, [%1];" : "=r"(v) : "l"(ctr) : "memory");
        while (v < goal) {
            __nanosleep(32);
            asm volatile("ld.acquire.gpu.u32 %0, [%1];" : "=r"(v) : "l"(ctr) : "memory");
        }
    }
    __syncthreads();
}

// ---------------- precompute: gx = x @ [Wg_x | Wc_x] + [bg | bc], remapped ----
__global__ void __launch_bounds__(NTHR) precompute_kernel(
    const float* __restrict__ x, const float* __restrict__ Wg,
    const float* __restrict__ bg, const float* __restrict__ Wc,
    const float* __restrict__ bc, const float* __restrict__ h0)
{
    __shared__ float2 as2[8 * 128];
    __shared__ float2 bs2[8 * 64];

    const int tid = threadIdx.x;

    if (blockIdx.x == 0 && blockIdx.y == 0) {
        for (int i = tid; i < BB * HH; i += NTHR) g_h[i] = h0[i];
        if (tid < 16) g_ctr[tid * 32] = 0u;
    }

    const int bx = blockIdx.x;          // 0..11 (8 Wg tiles, 4 Wc tiles)
    const int m0 = blockIdx.y * 128;

    const float* Wp; const float* bias; int ldw, n0;
    if (bx < 8) { Wp = Wg; bias = bg; ldw = 1024; n0 = bx * 128; }
    else        { Wp = Wc; bias = bc; ldw = 512;  n0 = (bx - 8) * 128; }

    const int tx = tid & 15, ty = tid >> 4;
    const int arow = tid >> 1, acol = (tid & 1) * 4;
    const int bkrow = tid >> 5, bcol2 = (tid & 31) * 2;

    const float* aptr = x + (size_t)(m0 + arow) * IND + acol;
    const float* bptr = Wp + (size_t)bkrow * ldw + n0 + bcol2 * 2;

    float4 areg = *(const float4*)aptr;
    float4 breg = *(const float4*)bptr;

    ull acc[8][4];
#pragma unroll
    for (int i = 0; i < 8; ++i)
#pragma unroll
        for (int j = 0; j < 4; ++j) acc[i][j] = 0ULL;

    for (int kt = 0; kt < IND / 8; ++kt) {
        as2[(acol + 0) * 128 + arow] = make_float2(areg.x, areg.x);
        as2[(acol + 1) * 128 + arow] = make_float2(areg.y, areg.y);
        as2[(acol + 2) * 128 + arow] = make_float2(areg.z, areg.z);
        as2[(acol + 3) * 128 + arow] = make_float2(areg.w, areg.w);
        *(float4*)&bs2[bkrow * 64 + bcol2] = breg;
        __syncthreads();
        if (kt + 1 < IND / 8) {
            areg = *(const float4*)(aptr + (kt + 1) * 8);
            breg = *(const float4*)(bptr + (size_t)(kt + 1) * 8 * ldw);
        }
#pragma unroll
        for (int k = 0; k < 8; ++k) {
            ulonglong2 a01 = *(const ulonglong2*)&as2[k * 128 + ty * 8];
            ulonglong2 a23 = *(const ulonglong2*)&as2[k * 128 + ty * 8 + 2];
            ulonglong2 a45 = *(const ulonglong2*)&as2[k * 128 + ty * 8 + 4];
            ulonglong2 a67 = *(const ulonglong2*)&as2[k * 128 + ty * 8 + 6];
            ulonglong2 b01 = *(const ulonglong2*)&bs2[k * 64 + tx * 4];
            ulonglong2 b23 = *(const ulonglong2*)&bs2[k * 64 + tx * 4 + 2];
            ull av[8] = {a01.x, a01.y, a23.x, a23.y, a45.x, a45.y, a67.x, a67.y};
            ull bv[4] = {b01.x, b01.y, b23.x, b23.y};
#pragma unroll
            for (int i = 0; i < 8; ++i)
#pragma unroll
                for (int j = 0; j < 4; ++j)
                    acc[i][j] = ffma2(av[i], bv[j], acc[i][j]);
        }
        __syncthreads();
    }

    float bvl[8];
#pragma unroll
    for (int j = 0; j < 8; ++j) bvl[j] = bias[n0 + tx * 8 + j];

    // Destination remap: (bx, tx) -> (cta, slot). 8 consecutive cols stay in
    // one 32-col block, so slot is contiguous.
    int cta, slot;
    if (bx < 8) {
        int gcol = bx * 128 + tx * 8;
        if (gcol < 512) { cta = gcol >> 5; slot = gcol & 31; }
        else { int rc = gcol - 512; cta = rc >> 5; slot = 32 + (rc & 31); }
    } else {
        int ccol = (bx - 8) * 128 + tx * 8;
        cta = ccol >> 5; slot = 64 + (ccol & 31);
    }

#pragma unroll
    for (int i = 0; i < 8; ++i) {
        int m = m0 + ty * 8 + i;
        int t = m >> 6, b = m & 63, g = b >> 3, r = b & 7;
        float* op = g_gx + (((size_t)t * 8 + g) * 16 + cta) * 768 + r * 96 + slot;
        float2 c0, c1, c2, c3;
        c0.x = __uint_as_float((unsigned)acc[i][0]); c0.y = __uint_as_float((unsigned)(acc[i][0] >> 32));
        c1.x = __uint_as_float((unsigned)acc[i][1]); c1.y = __uint_as_float((unsigned)(acc[i][1] >> 32));
        c2.x = __uint_as_float((unsigned)acc[i][2]); c2.y = __uint_as_float((unsigned)(acc[i][2] >> 32));
        c3.x = __uint_as_float((unsigned)acc[i][3]); c3.y = __uint_as_float((unsigned)(acc[i][3] >> 32));
        *(float4*)(op)     = make_float4(c0.x + bvl[0], c0.y + bvl[1],
                                         c1.x + bvl[2], c1.y + bvl[3]);
        *(float4*)(op + 4) = make_float4(c2.x + bvl[4], c2.y + bvl[5],
                                         c3.x + bvl[6], c3.y + bvl[7]);
    }
}

// ---------------- persistent scan kernel ----------------
// 128 CTAs x 256 thr, 1/SM. Group g = bid>>4 owns batch rows [g*8, g*8+8).
// cid = bid&15: z cols [cid*32,+32), r cols [512+cid*32,+32), cand cols [cid*32,+32).
// smem (floats): wg 64x512 = 32768 | wc 32x512 = 16384 | hst 8x512 = 4096 (reused
// for rh) | P 4096 | zb 256.  Total 57600 floats = 230400 B.
#define SM_WG  0
#define SM_WC  32768
#define SM_HST 49152
#define SM_P   53248
#define SM_Z   57344
#define SMEM_FLOATS 57600
#define SMEM_BYTES (SMEM_FLOATS * 4)

__global__ void __launch_bounds__(NTHR, 1) scan_kernel(
    const float* __restrict__ Wg, const float* __restrict__ Wc,
    float* __restrict__ out, int write_outputs, int write_hlast)
{
    extern __shared__ float sm[];
    float* wg  = sm + SM_WG;
    float* wc  = sm + SM_WC;
    float* hst = sm + SM_HST;
    float* P   = sm + SM_P;
    float* zb  = sm + SM_Z;

    const int tid = threadIdx.x;
    const int g   = blockIdx.x >> 4;
    const int cid = blockIdx.x & 15;
    const int r0  = g * 8;
    const int c32 = cid * 32;

    // ---- load recurrent weight slabs once (swizzled, k-contiguous per col) ----
    for (int idx = tid; idx < 64 * 512; idx += NTHR) {
        int k = idx >> 6, c = idx & 63;
        int gc = (c < 32) ? (c32 + c) : (512 + c32 + (c - 32));
        float v = Wg[(size_t)(512 + k) * 1024 + gc];
        wg[c * 512 + (((k >> 2) ^ ((c >> 2) & 7)) << 2) + (k & 3)] = v;
    }
    for (int idx = tid; idx < 32 * 512; idx += NTHR) {
        int k = idx >> 5, c = idx & 31;
        float v = Wc[(size_t)(512 + k) * 512 + c32 + c];
        wc[c * 512 + (((k >> 2) ^ ((c >> 2) & 7)) << 2) + (k & 3)] = v;
    }
    __syncthreads();

    // phase1 mapping: warp ks = k-slice (64 k), lane = (rg:2) x (cg:16), tile 4x4
    const int ks = tid >> 5;
    const int ln = tid & 31;
    const int rg = ln >> 4, cg = ln & 15;
    // phase2 mapping: lane = (rg2:4) x (cg2:8), tile 2x4
    const int rg2 = ln >> 3, cg2 = ln & 7;

    // phase1 epilogue outputs (2 per thread): v = ks + 8*vv
    int row1[2], col1[2];
#pragma unroll
    for (int vv = 0; vv < 2; ++vv) {
        int v = ks + 8 * vv;
        row1[vv] = rg * 4 + (v >> 2);
        col1[vv] = cg * 4 + (v & 3);
    }
    // phase2 epilogue output (1 per thread): v2 = ks
    const int v2   = ks;
    const int row2 = rg2 * 2 + (v2 >> 2);
    const int col2 = cg2 * 4 + (v2 & 3);
    const int jj2  = c32 + col2;
    const int b2   = r0 + row2;

    unsigned* ctrA = g_ctr + (g * 2) * 32;
    unsigned* ctrB = g_ctr + (g * 2 + 1) * 32;

    for (int t = 0; t < SEQ; ++t) {
        const float* gblk = g_gx + (((size_t)t * 8 + g) * 16 + cid) * 768;
        // prefetch gx pre-activations (consumed ~2-3k cyc later)
        float gxzr0 = __ldcg(gblk + row1[0] * 96 + col1[0]);
        float gxzr1 = __ldcg(gblk + row1[1] * 96 + col1[1]);
        float gxc   = __ldcg(gblk + row2 * 96 + 64 + col2);

        // ---- stage h: 8 rows x 512 (16 KB), swizzled ----
#pragma unroll
        for (int it = 0; it < 4; ++it) {
            int id = tid + it * NTHR;
            int lr = id >> 7, kc = id & 127;
            float4 v = __ldcg((const float4*)(g_h + (size_t)(r0 + lr) * HH + kc * 4));
            *(float4*)&hst[lr * 512 + ((kc ^ (lr & 7)) << 2)] = v;
        }
        __syncthreads();

        // ---- phase1: gates GEMM, thread = 4 rows x 4 cols x 64 k ----
        {
            ull acc[4][4];
#pragma unroll
            for (int i = 0; i < 4; ++i)
#pragma unroll
                for (int j = 0; j < 4; ++j) acc[i][j] = 0ULL;

            const int kc0 = ks * 16;
#pragma unroll 4
            for (int tt = 0; tt < 16; ++tt) {
                int kc = kc0 + tt;
                ulonglong2 hv[4], wv[4];
#pragma unroll
                for (int i = 0; i < 4; ++i) {
                    int row = rg * 4 + i;
                    hv[i] = *(const ulonglong2*)&hst[row * 512 + ((kc ^ (row & 7)) << 2)];
                }
#pragma unroll
                for (int j = 0; j < 4; ++j) {
                    int col = cg * 4 + j;
                    wv[j] = *(const ulonglong2*)&wg[col * 512 + ((kc ^ (cg & 7)) << 2)];
                }
#pragma unroll
                for (int i = 0; i < 4; ++i)
#pragma unroll
                    for (int j = 0; j < 4; ++j) {
                        acc[i][j] = ffma2(hv[i].x, wv[j].x, acc[i][j]);
                        acc[i][j] = ffma2(hv[i].y, wv[j].y, acc[i][j]);
                    }
            }
#pragma unroll
            for (int i = 0; i < 4; ++i)
#pragma unroll
                for (int j = 0; j < 4; ++j)
                    P[(ks * 16 + i * 4 + j) * 32 + ln] = ull_sum(acc[i][j]);
        }
        __syncthreads();

        // ---- phase1 reduce + epilogue (z local, rh -> global) ----
#pragma unroll
        for (int vv = 0; vv < 2; ++vv) {
            int v = ks + 8 * vv;
            float s = 0.f;
#pragma unroll
            for (int q = 0; q < 8; ++q) s += P[(q * 16 + v) * 32 + ln];
            float tot = s + (vv ? gxzr1 : gxzr0);
            float sg = sigmoidf_(tot);
            int row = row1[vv], col = col1[vv];
            if (col < 32) {
                zb[row * 32 + col] = sg;
            } else {
                int jj = c32 + (col - 32);
                float hv = hst[row * 512 + (((jj >> 2) ^ (row & 7)) << 2) + (jj & 3)];
                __stcg(g_rh + (size_t)(r0 + row) * HH + jj, sg * hv);
            }
        }
        // save own h_prev for the phase2 update before hst is overwritten
        float hprev = hst[row2 * 512 + (((jj2 >> 2) ^ (row2 & 7)) << 2) + (jj2 & 3)];

        bar_arrive(ctrA);
        bar_wait(ctrA, (unsigned)(t + 1) * 16u);

        // ---- stage rh into hst (overwrite) ----
#pragma unroll
        for (int it = 0; it < 4; ++it) {
            int id = tid + it * NTHR;
            int lr = id >> 7, kc = id & 127;
            float4 v = __ldcg((const float4*)(g_rh + (size_t)(r0 + lr) * HH + kc * 4));
            *(float4*)&hst[lr * 512 + ((kc ^ (lr & 7)) << 2)] = v;
        }
        __syncthreads();

        // ---- phase2: candidate GEMM, thread = 2 rows x 4 cols x 64 k ----
        {
            ull acc2[2][4];
#pragma unroll
            for (int i = 0; i < 2; ++i)
#pragma unroll
                for (int j = 0; j < 4; ++j) acc2[i][j] = 0ULL;

            const int kc0 = ks * 16;
#pragma unroll 4
            for (int tt = 0; tt < 16; ++tt) {
                int kc = kc0 + tt;
                ulonglong2 hv[2], wv[4];
#pragma unroll
                for (int i = 0; i < 2; ++i) {
                    int row = rg2 * 2 + i;
                    hv[i] = *(const ulonglong2*)&hst[row * 512 + ((kc ^ (row & 7)) << 2)];
                }
#pragma unroll
                for (int j = 0; j < 4; ++j) {
                    int col = cg2 * 4 + j;
                    wv[j] = *(const ulonglong2*)&wc[col * 512 + ((kc ^ (cg2 & 7)) << 2)];
                }
#pragma unroll
                for (int i = 0; i < 2; ++i)
#pragma unroll
                    for (int j = 0; j < 4; ++j) {
                        acc2[i][j] = ffma2(hv[i].x, wv[j].x, acc2[i][j]);
                        acc2[i][j] = ffma2(hv[i].y, wv[j].y, acc2[i][j]);
                    }
            }
#pragma unroll
            for (int i = 0; i < 2; ++i)
#pragma unroll
                for (int j = 0; j < 4; ++j)
                    P[(ks * 8 + i * 4 + j) * 32 + ln] = ull_sum(acc2[i][j]);
        }
        __syncthreads();

        // ---- phase2 reduce + h update ----
        {
            float s = 0.f;
#pragma unroll
            for (int q = 0; q < 8; ++q) s += P[(q * 8 + v2) * 32 + ln];
            float cand = tanhf_(s + gxc);
            float z = zb[row2 * 32 + col2];
            float hn = fmaf(z, cand - hprev, hprev);   // (1-z)*h + z*cand
            __stcg(g_h + (size_t)b2 * HH + jj2, hn);
            if (write_outputs)
                out[((size_t)t * BB + b2) * HH + jj2] = hn;
            if (write_hlast && t == SEQ - 1) {
                size_t off = write_outputs ? (size_t)SEQ * BB * HH : 0;
                out[off + (size_t)b2 * HH + jj2] = hn;
            }
        }

        bar_arrive(ctrB);
        bar_wait(ctrB, (unsigned)(t + 1) * 16u);
    }
}

// ---------------- launch ----------------
extern "C" void kernel_launch(void* const* d_in, const int* in_sizes, int n_in,
                              void* d_out, int out_size) {
    const float* x  = (const float*)d_in[0];
    const float* h0 = (const float*)d_in[1];
    const float* Wg = (const float*)d_in[2];
    const float* bg = (const float*)d_in[3];
    const float* Wc = (const float*)d_in[4];
    const float* bc = (const float*)d_in[5];
    float* out = (float*)d_out;

    cudaFuncSetAttribute(scan_kernel, cudaFuncAttributeMaxDynamicSharedMemorySize,
                         SMEM_BYTES);

    long long full = (long long)SEQ * BB * HH;
    int write_outputs = (out_size >= full) ? 1 : 0;
    long long hlast_off = write_outputs ? full : 0;
    int write_hlast = (out_size >= hlast_off + BB * HH) ? 1 : 0;

    dim3 pgrid(12, 1024);
    precompute_kernel<<<pgrid, NTHR>>>(x, Wg, bg, Wc, bc, h0);
    scan_kernel<<<NCTA, NTHR, SMEM_BYTES>>>(Wg, Wc, out, write_outputs, write_hlast);
}